// round 6
// baseline (speedup 1.0000x reference)
#include <cuda_runtime.h>
#include <math.h>

#define NB   32      // batch
#define PP   196     // pixels
#define ENC  2048
#define DECD 512
#define ATT  512
#define EMB  256
#define NV   30000
#define LL   21
#define NT   20      // decode steps
#define XK   (EMB + ENC)   // 2304

typedef unsigned long long u64;

// ---------- packed f32x2 helpers (sm_103a) ----------
__device__ __forceinline__ u64 pack2(float lo, float hi) {
    u64 r; asm("mov.b64 %0, {%1, %2};" : "=l"(r) : "f"(lo), "f"(hi)); return r;
}
__device__ __forceinline__ void unpack2(u64 v, float& lo, float& hi) {
    asm("mov.b64 {%0, %1}, %2;" : "=f"(lo), "=f"(hi) : "l"(v));
}
__device__ __forceinline__ u64 ffma2(u64 a, u64 b, u64 c) {
    u64 d; asm("fma.rn.f32x2 %0, %1, %2, %3;" : "=l"(d) : "l"(a), "l"(b), "l"(c)); return d;
}
__device__ __forceinline__ u64 fadd2(u64 a, u64 b) {
    u64 d; asm("add.rn.f32x2 %0, %1, %2;" : "=l"(d) : "l"(a), "l"(b)); return d;
}

// ---------- persistent scratch (no cudaMalloc allowed) ----------
__device__ __align__(16) float g_att1 [NB * PP * ATT];     // 12.8 MB
__device__ __align__(16) float g_mean [NB * ENC];
__device__ __align__(16) float g_h    [NB * DECD];         // h0 only
__device__ __align__(16) float g_c    [NB * DECD];
__device__ __align__(16) float g_x    [NB * XK];
__device__ __align__(16) float g_hall [NT * NB * DECD];    // h_t, rows m = t*32+b
__device__ __align__(16) float g_alpha[NB * PP];

// ============================================================
// mean over P
// ============================================================
__global__ void mean_kernel(const float* __restrict__ enc, float* __restrict__ mean)
{
    int b = blockIdx.x;
    for (int k = threadIdx.x; k < ENC; k += 256) {
        const float* p0 = enc + (size_t)b * PP * ENC + k;
        float s = 0.f;
        #pragma unroll 4
        for (int p = 0; p < PP; p++) s += p0[(size_t)p * ENC];
        mean[b * ENC + k] = s * (1.0f / PP);
    }
}

// ============================================================
// Big tiled GEMM (R4-proven): C[M,Ntot] = A[M,K] @ W[Ntot,K]^T + bias
// 128x64 tile, BK=32, software-pipelined, f32x2 accumulators.
// remap=0: C[m*ldc + n].  remap=1 (preds): row m=t*32+b -> C[(b*NT+t)*Ntot+n].
// m_base: global row offset for chunked launches.
// ============================================================
__global__ __launch_bounds__(256, 3) void gemm_kernel(
    const float* __restrict__ A, const float* __restrict__ W,
    const float* __restrict__ bias, float* __restrict__ C,
    int K, int Ntot, int ldc, int remap, int m_base)
{
    __shared__ __align__(16) float As[32][128];
    __shared__ __align__(16) float Bs[32][64];
    const int tid = threadIdx.x;
    const int m0  = m_base + blockIdx.y * 128;
    const int n0  = blockIdx.x * 64;
    const int tmb = (tid & 15) * 2;
    const int tn  = (tid >> 4) * 4;

    u64 acc[4][4];
    #pragma unroll
    for (int i = 0; i < 4; i++)
        #pragma unroll
        for (int j = 0; j < 4; j++) acc[i][j] = 0ull;

    float4 av[4], bv[2];
    #pragma unroll
    for (int r = 0; r < 4; r++) {
        int f = tid + r * 256; int m = f >> 3; int c = f & 7;
        av[r] = *(const float4*)(A + (size_t)(m0 + m) * K + c * 4);
    }
    #pragma unroll
    for (int r = 0; r < 2; r++) {
        int f = tid + r * 256; int n = n0 + (f >> 3); int c = f & 7;
        if (n >= Ntot) n = Ntot - 1;
        bv[r] = *(const float4*)(W + (size_t)n * K + c * 4);
    }

    #pragma unroll 1
    for (int k0 = 0; k0 < K; k0 += 32) {
        __syncthreads();
        #pragma unroll
        for (int r = 0; r < 4; r++) {
            int f = tid + r * 256; int m = f >> 3; int c = f & 7;
            As[c*4+0][m] = av[r].x; As[c*4+1][m] = av[r].y;
            As[c*4+2][m] = av[r].z; As[c*4+3][m] = av[r].w;
        }
        #pragma unroll
        for (int r = 0; r < 2; r++) {
            int f = tid + r * 256; int n = f >> 3; int c = f & 7;
            Bs[c*4+0][n] = bv[r].x; Bs[c*4+1][n] = bv[r].y;
            Bs[c*4+2][n] = bv[r].z; Bs[c*4+3][n] = bv[r].w;
        }
        __syncthreads();
        if (k0 + 32 < K) {
            #pragma unroll
            for (int r = 0; r < 4; r++) {
                int f = tid + r * 256; int m = f >> 3; int c = f & 7;
                av[r] = *(const float4*)(A + (size_t)(m0 + m) * K + k0 + 32 + c * 4);
            }
            #pragma unroll
            for (int r = 0; r < 2; r++) {
                int f = tid + r * 256; int n = n0 + (f >> 3); int c = f & 7;
                if (n >= Ntot) n = Ntot - 1;
                bv[r] = *(const float4*)(W + (size_t)n * K + k0 + 32 + c * 4);
            }
        }
        #pragma unroll 8
        for (int k = 0; k < 32; k++) {
            u64 a2[4];
            #pragma unroll
            for (int i = 0; i < 4; i++)
                a2[i] = *(const u64*)&As[k][tmb + 32 * i];
            float4 b4 = *(const float4*)&Bs[k][tn];
            u64 bd[4] = { pack2(b4.x, b4.x), pack2(b4.y, b4.y),
                          pack2(b4.z, b4.z), pack2(b4.w, b4.w) };
            #pragma unroll
            for (int i = 0; i < 4; i++)
                #pragma unroll
                for (int j = 0; j < 4; j++)
                    acc[i][j] = ffma2(a2[i], bd[j], acc[i][j]);
        }
    }
    #pragma unroll
    for (int i = 0; i < 4; i++) {
        int m = m0 + tmb + 32 * i;
        #pragma unroll
        for (int j = 0; j < 4; j++) {
            int n = n0 + tn + j;
            if (n >= Ntot) continue;
            float lo, hi; unpack2(acc[i][j], lo, hi);
            float bb = bias[n];
            if (remap) {
                int t0 = m >> 5,  b0 = m & 31;
                int t1 = (m + 1) >> 5, b1 = (m + 1) & 31;
                C[(size_t)(b0 * NT + t0) * Ntot + n] = lo + bb;
                C[(size_t)(b1 * NT + t1) * Ntot + n] = hi + bb;
            } else {
                C[(size_t)m       * ldc + n] = lo + bb;
                C[(size_t)(m + 1) * ldc + n] = hi + bb;
            }
        }
    }
}

// ============================================================
// Skinny GEMM (init h0/c0 only): out[b][n] = b1[n] + A1[b]·W1[n]
// ============================================================
__global__ __launch_bounds__(256) void skinny_gemm_kernel(
    const float* __restrict__ A1, const float* __restrict__ W1, int K1,
    const float* __restrict__ bias1, float* __restrict__ out, int ldc)
{
    __shared__ __align__(16) u64 xs[16][64];
    const int tid  = threadIdx.x;
    const int lane = tid & 31;
    const int w    = tid >> 5;
    const int ng   = w & 3;
    const int bg   = w >> 2;
    const int n0   = blockIdx.x * 16 + ng * 4;
    const int b2s  = tid >> 4;
    const int c4   = tid & 15;

    u64 acc[8][4];
    #pragma unroll
    for (int i = 0; i < 8; i++)
        #pragma unroll
        for (int j = 0; j < 4; j++) acc[i][j] = 0ull;

    for (int k0 = 0; k0 < K1; k0 += 64) {
        float4 lo4 = *(const float4*)(A1 + (size_t)(2 * b2s)     * K1 + k0 + c4 * 4);
        float4 hi4 = *(const float4*)(A1 + (size_t)(2 * b2s + 1) * K1 + k0 + c4 * 4);
        __syncthreads();
        xs[b2s][c4*4+0] = pack2(lo4.x, hi4.x);
        xs[b2s][c4*4+1] = pack2(lo4.y, hi4.y);
        xs[b2s][c4*4+2] = pack2(lo4.z, hi4.z);
        xs[b2s][c4*4+3] = pack2(lo4.w, hi4.w);
        __syncthreads();
        const float* wp = W1 + k0 + lane;
        u64 wd0[4], wd1[4];
        #pragma unroll
        for (int j = 0; j < 4; j++) {
            const float* r = wp + (size_t)(n0 + j) * K1;
            float w0 = r[0], w1 = r[32];
            wd0[j] = pack2(w0, w0);
            wd1[j] = pack2(w1, w1);
        }
        #pragma unroll
        for (int i = 0; i < 8; i++) {
            u64 x0 = xs[bg * 8 + i][lane];
            u64 x1 = xs[bg * 8 + i][lane + 32];
            #pragma unroll
            for (int j = 0; j < 4; j++) {
                acc[i][j] = ffma2(x0, wd0[j], acc[i][j]);
                acc[i][j] = ffma2(x1, wd1[j], acc[i][j]);
            }
        }
    }
    #pragma unroll
    for (int i = 0; i < 8; i++)
        #pragma unroll
        for (int j = 0; j < 4; j++) {
            u64 v = acc[i][j];
            #pragma unroll
            for (int o = 16; o > 0; o >>= 1)
                v = fadd2(v, __shfl_xor_sync(0xffffffffu, v, o));
            acc[i][j] = v;
        }
    if (lane == 0) {
        #pragma unroll
        for (int i = 0; i < 8; i++) {
            int b = (bg * 8 + i) * 2;
            #pragma unroll
            for (int j = 0; j < 4; j++) {
                int n = n0 + j;
                float bb = bias1[n];
                float lo, hi; unpack2(acc[i][j], lo, hi);
                out[(size_t)b       * ldc + n] = lo + bb;
                out[(size_t)(b + 1) * ldc + n] = hi + bb;
            }
        }
    }
}

// ============================================================
// Fused attention: att2 (h·Wd^T+bd) + escore + softmax + alpha out +
// embedding gather. One block per batch element. (awe kept separate.)
// ============================================================
__global__ __launch_bounds__(256) void att_fused_kernel(
    const float* __restrict__ att1, const float* __restrict__ h_in,
    const float* __restrict__ Wd,  const float* __restrict__ bd,
    const float* __restrict__ Wf,  const float* __restrict__ bf,
    float* __restrict__ alpha, float* __restrict__ out_alpha, int t,
    const int* __restrict__ captions, const float* __restrict__ emb,
    float* __restrict__ xbuf)
{
    __shared__ __align__(16) float sH[DECD];
    __shared__ __align__(16) float sA[ATT];
    __shared__ __align__(16) float sW[ATT];
    __shared__ float sE[256];
    __shared__ float red[256];
    __shared__ int s_idx;

    const int b = blockIdx.x, tid = threadIdx.x;

    sH[tid]       = h_in[(size_t)b * DECD + tid];
    sH[tid + 256] = h_in[(size_t)b * DECD + tid + 256];
    sW[tid]       = Wf[tid];
    sW[tid + 256] = Wf[tid + 256];
    sE[tid] = -3.4e38f;
    __syncthreads();

    // att2[a] = bd[a] + sum_k h[k] * Wd[a][k]
    #pragma unroll
    for (int r = 0; r < 2; r++) {
        int a = tid + r * 256;
        const float4* wr = (const float4*)(Wd + (size_t)a * DECD);
        const float4* hh = (const float4*)sH;
        float acc = 0.f;
        #pragma unroll 8
        for (int kk = 0; kk < DECD / 4; kk++) {
            float4 wv = wr[kk], hv = hh[kk];
            acc += wv.x * hv.x + wv.y * hv.y + wv.z * hv.z + wv.w * hv.w;
        }
        sA[a] = acc + bd[a];
    }
    __syncthreads();

    // escore per warp
    const int w = tid >> 5, lane = tid & 31;
    for (int p = w; p < PP; p += 8) {
        const float4* row = (const float4*)(att1 + ((size_t)b * PP + p) * ATT);
        const float4* a4  = (const float4*)sA;
        const float4* w4  = (const float4*)sW;
        float acc = 0.f;
        #pragma unroll
        for (int c = lane; c < ATT / 4; c += 32) {
            float4 v = row[c], h = a4[c], f = w4[c];
            acc += fmaxf(v.x + h.x, 0.f) * f.x + fmaxf(v.y + h.y, 0.f) * f.y
                 + fmaxf(v.z + h.z, 0.f) * f.z + fmaxf(v.w + h.w, 0.f) * f.w;
        }
        #pragma unroll
        for (int o = 16; o > 0; o >>= 1) acc += __shfl_xor_sync(0xffffffffu, acc, o);
        if (lane == 0) sE[p] = acc + bf[0];
    }
    __syncthreads();

    // softmax over sE[0..195]
    float v = sE[tid];
    red[tid] = v; __syncthreads();
    #pragma unroll
    for (int s = 128; s > 0; s >>= 1) {
        if (tid < s) red[tid] = fmaxf(red[tid], red[tid + s]);
        __syncthreads();
    }
    float mx = red[0]; __syncthreads();
    float ex = (tid < PP) ? expf(v - mx) : 0.f;
    red[tid] = ex; __syncthreads();
    #pragma unroll
    for (int s = 128; s > 0; s >>= 1) {
        if (tid < s) red[tid] += red[tid + s];
        __syncthreads();
    }
    float inv = 1.0f / red[0];
    if (tid < PP) {
        float a = ex * inv;
        alpha[b * PP + tid] = a;
        out_alpha[(size_t)(b * NT + t) * PP + tid] = a;
    }
    if (tid == 0) {
        // dtype hedge: int64 captions -> every odd 32-bit word is 0
        bool is64 = true;
        #pragma unroll
        for (int i = 0; i < 32; i++)
            if (captions[2 * i + 1] != 0) is64 = false;
        int pos = b * LL + t;
        s_idx = is64 ? captions[2 * pos] : captions[pos];
    }
    __syncthreads();
    xbuf[(size_t)b * XK + tid] = emb[(size_t)s_idx * EMB + tid];  // 256 == EMB
}

// ============================================================
// awe[b][k] = sum_p alpha[b,p] * enc[b,p,k]  -> x buffer at +EMB
// ============================================================
__global__ void awe_kernel(const float* __restrict__ enc,
                           const float* __restrict__ alpha,
                           float* __restrict__ xbuf)
{
    __shared__ float al[PP];
    int b = blockIdx.y;
    int k = blockIdx.x * 256 + threadIdx.x;
    if (threadIdx.x < PP) al[threadIdx.x] = alpha[b * PP + threadIdx.x];
    __syncthreads();
    const float* ep = enc + (size_t)b * PP * ENC + k;
    float acc = 0.f;
    #pragma unroll 4
    for (int p = 0; p < PP; p++) acc += al[p] * ep[(size_t)p * ENC];
    xbuf[(size_t)b * XK + EMB + k] = acc;
}

// ============================================================
// Gates GEMM + fused LSTM. Warp ng handles column jcol = blockIdx*4+ng;
// its 4 "n" rows are the 4 gates (i,f,g,o) at jcol. Lane 0 applies the
// LSTM pointwise and writes h directly into hall[t].
// ============================================================
__global__ __launch_bounds__(256) void gates_lstm_kernel(
    const float* __restrict__ x,   const float* __restrict__ Wih,
    const float* __restrict__ h_in, const float* __restrict__ Whh,
    const float* __restrict__ bih, const float* __restrict__ bhh,
    float* __restrict__ c, float* __restrict__ h_out)
{
    __shared__ __align__(16) u64 xs[16][64];
    const int tid  = threadIdx.x;
    const int lane = tid & 31;
    const int w    = tid >> 5;
    const int ng   = w & 3;
    const int bg   = w >> 2;
    const int jcol = blockIdx.x * 4 + ng;
    const int b2s  = tid >> 4;
    const int c4   = tid & 15;

    int nj[4];
    #pragma unroll
    for (int j = 0; j < 4; j++) nj[j] = j * DECD + jcol;

    u64 acc[8][4];
    #pragma unroll
    for (int i = 0; i < 8; i++)
        #pragma unroll
        for (int j = 0; j < 4; j++) acc[i][j] = 0ull;

    #pragma unroll 1
    for (int seg = 0; seg < 2; seg++) {
        const float* A = seg ? h_in : x;
        const float* W = seg ? Whh  : Wih;
        const int    K = seg ? DECD : XK;
        for (int k0 = 0; k0 < K; k0 += 64) {
            float4 lo4 = *(const float4*)(A + (size_t)(2 * b2s)     * K + k0 + c4 * 4);
            float4 hi4 = *(const float4*)(A + (size_t)(2 * b2s + 1) * K + k0 + c4 * 4);
            __syncthreads();
            xs[b2s][c4*4+0] = pack2(lo4.x, hi4.x);
            xs[b2s][c4*4+1] = pack2(lo4.y, hi4.y);
            xs[b2s][c4*4+2] = pack2(lo4.z, hi4.z);
            xs[b2s][c4*4+3] = pack2(lo4.w, hi4.w);
            __syncthreads();
            const float* wp = W + k0 + lane;
            u64 wd0[4], wd1[4];
            #pragma unroll
            for (int j = 0; j < 4; j++) {
                const float* r = wp + (size_t)nj[j] * K;
                float w0 = r[0], w1 = r[32];
                wd0[j] = pack2(w0, w0);
                wd1[j] = pack2(w1, w1);
            }
            #pragma unroll
            for (int i = 0; i < 8; i++) {
                u64 x0 = xs[bg * 8 + i][lane];
                u64 x1 = xs[bg * 8 + i][lane + 32];
                #pragma unroll
                for (int j = 0; j < 4; j++) {
                    acc[i][j] = ffma2(x0, wd0[j], acc[i][j]);
                    acc[i][j] = ffma2(x1, wd1[j], acc[i][j]);
                }
            }
        }
    }
    #pragma unroll
    for (int i = 0; i < 8; i++)
        #pragma unroll
        for (int j = 0; j < 4; j++) {
            u64 v = acc[i][j];
            #pragma unroll
            for (int o = 16; o > 0; o >>= 1)
                v = fadd2(v, __shfl_xor_sync(0xffffffffu, v, o));
            acc[i][j] = v;
        }
    if (lane == 0) {
        #pragma unroll
        for (int i = 0; i < 8; i++) {
            int b0 = (bg * 8 + i) * 2;
            float gv[4][2];
            #pragma unroll
            for (int j = 0; j < 4; j++) {
                float bb = bih[nj[j]] + bhh[nj[j]];
                float lo, hi; unpack2(acc[i][j], lo, hi);
                gv[j][0] = lo + bb; gv[j][1] = hi + bb;
            }
            #pragma unroll
            for (int hs = 0; hs < 2; hs++) {
                int bb = b0 + hs;
                float ig = gv[0][hs], fg = gv[1][hs], gg = gv[2][hs], og = gv[3][hs];
                float si = 1.f / (1.f + expf(-ig));
                float sf = 1.f / (1.f + expf(-fg));
                float so = 1.f / (1.f + expf(-og));
                float co = c[(size_t)bb * DECD + jcol];
                float cn = sf * co + si * tanhf(gg);
                float hn = so * tanhf(cn);
                c[(size_t)bb * DECD + jcol]     = cn;
                h_out[(size_t)bb * DECD + jcol] = hn;
            }
        }
    }
}

// ============================================================
extern "C" void kernel_launch(void* const* d_in, const int* in_sizes, int n_in,
                              void* d_out, int out_size)
{
    const float* enc  = (const float*)d_in[0];
    const int*   caps = (const int*)  d_in[1];
    const float* emb  = (const float*)d_in[3];
    const float* We   = (const float*)d_in[4];
    const float* be   = (const float*)d_in[5];
    const float* Wd   = (const float*)d_in[6];
    const float* bd   = (const float*)d_in[7];
    const float* Wf   = (const float*)d_in[8];
    const float* bf   = (const float*)d_in[9];
    const float* Wih  = (const float*)d_in[10];
    const float* bih  = (const float*)d_in[11];
    const float* Whh  = (const float*)d_in[12];
    const float* bhh  = (const float*)d_in[13];
    const float* Wfc  = (const float*)d_in[14];
    const float* bfc  = (const float*)d_in[15];
    const float* Wh0  = (const float*)d_in[16];
    const float* bh0  = (const float*)d_in[17];
    const float* Wc0  = (const float*)d_in[18];
    const float* bc0  = (const float*)d_in[19];

    float* out       = (float*)d_out;                  // predictions [32,20,30000]
    float* out_alpha = out + (size_t)NB * NT * NV;     // alphas      [32,20,196]

    float *p_att1, *p_mean, *p_h, *p_c, *p_x, *p_hall, *p_alpha;
    cudaGetSymbolAddress((void**)&p_att1,  g_att1);
    cudaGetSymbolAddress((void**)&p_mean,  g_mean);
    cudaGetSymbolAddress((void**)&p_h,     g_h);
    cudaGetSymbolAddress((void**)&p_c,     g_c);
    cudaGetSymbolAddress((void**)&p_x,     g_x);
    cudaGetSymbolAddress((void**)&p_hall,  g_hall);
    cudaGetSymbolAddress((void**)&p_alpha, g_alpha);

    // Fork stream + events (created per call; never destroyed — capture may
    // still reference them after this function returns. No device memory.)
    cudaStream_t s2;
    cudaStreamCreateWithFlags(&s2, cudaStreamNonBlocking);
    cudaEvent_t evMean, evInit, evStep[5], evDone;
    cudaEventCreateWithFlags(&evMean, cudaEventDisableTiming);
    cudaEventCreateWithFlags(&evInit, cudaEventDisableTiming);
    for (int g = 0; g < 5; g++) cudaEventCreateWithFlags(&evStep[g], cudaEventDisableTiming);
    cudaEventCreateWithFlags(&evDone, cudaEventDisableTiming);

    // ---- init: mean on s0; h0/c0 on s2 concurrent with att1 on s0 ----
    mean_kernel<<<NB, 256>>>(enc, p_mean);
    cudaEventRecord(evMean, 0);
    cudaStreamWaitEvent(s2, evMean, 0);
    skinny_gemm_kernel<<<DECD / 16, 256, 0, s2>>>(p_mean, Wh0, ENC, bh0, p_h, DECD);
    skinny_gemm_kernel<<<DECD / 16, 256, 0, s2>>>(p_mean, Wc0, ENC, bc0, p_c, DECD);
    cudaEventRecord(evInit, s2);

    gemm_kernel<<<dim3(ATT / 64, (NB * PP) / 128), 256>>>(enc, We, be, p_att1,
                                                          ENC, ATT, ATT, 0, 0);
    cudaStreamWaitEvent(0, evInit, 0);

    // ---- decode loop: 3 launches/step; preds chunks overlap on s2 ----
    for (int t = 0; t < NT; t++) {
        const float* h_in  = (t == 0) ? p_h : (p_hall + (size_t)(t - 1) * NB * DECD);
        float*       h_out = p_hall + (size_t)t * NB * DECD;
        att_fused_kernel<<<NB, 256>>>(p_att1, h_in, Wd, bd, Wf, bf,
                                      p_alpha, out_alpha, t, caps, emb, p_x);
        awe_kernel<<<dim3(ENC / 256, NB), 256>>>(enc, p_alpha, p_x);
        gates_lstm_kernel<<<DECD / 4, 256>>>(p_x, Wih, h_in, Whh,
                                             bih, bhh, p_c, h_out);
        if ((t & 3) == 3) {
            int g = t >> 2;                       // chunk covers steps 4g..4g+3
            cudaEventRecord(evStep[g], 0);
            cudaStreamWaitEvent(s2, evStep[g], 0);
            gemm_kernel<<<dim3((NV + 63) / 64, 1), 256, 0, s2>>>(
                p_hall, Wfc, bfc, out, DECD, NV, 0, 1, g * 128);
        }
    }

    // ---- join ----
    cudaEventRecord(evDone, s2);
    cudaStreamWaitEvent(0, evDone, 0);
}

// round 7
// speedup vs baseline: 1.5392x; 1.5392x over previous
#include <cuda_runtime.h>
#include <math.h>

#define NB   32      // batch
#define PP   196     // pixels
#define ENC  2048
#define DECD 512
#define ATT  512
#define EMB  256
#define NV   30000
#define LL   21
#define NT   20      // decode steps
#define XK   (EMB + ENC)   // 2304

typedef unsigned long long u64;

// ---------- packed f32x2 helpers (sm_103a) ----------
__device__ __forceinline__ u64 pack2(float lo, float hi) {
    u64 r; asm("mov.b64 %0, {%1, %2};" : "=l"(r) : "f"(lo), "f"(hi)); return r;
}
__device__ __forceinline__ void unpack2(u64 v, float& lo, float& hi) {
    asm("mov.b64 {%0, %1}, %2;" : "=f"(lo), "=f"(hi) : "l"(v));
}
__device__ __forceinline__ u64 ffma2(u64 a, u64 b, u64 c) {
    u64 d; asm("fma.rn.f32x2 %0, %1, %2, %3;" : "=l"(d) : "l"(a), "l"(b), "l"(c)); return d;
}
__device__ __forceinline__ u64 fadd2(u64 a, u64 b) {
    u64 d; asm("add.rn.f32x2 %0, %1, %2;" : "=l"(d) : "l"(a), "l"(b)); return d;
}
__device__ __forceinline__ unsigned to_tf32(float f) {
    unsigned r; asm("cvt.rna.tf32.f32 %0, %1;" : "=r"(r) : "f"(f)); return r;
}

// ---------- persistent scratch (no cudaMalloc allowed) ----------
__device__ __align__(16) float g_att1 [NB * PP * ATT];     // 12.8 MB
__device__ __align__(16) float g_mean [NB * ENC];
__device__ __align__(16) float g_h    [NB * DECD];
__device__ __align__(16) float g_c    [NB * DECD];
__device__ __align__(16) float g_att2 [NB * ATT];
__device__ __align__(16) float g_alpha[NB * PP];
__device__ __align__(16) float g_x    [NB * XK];
__device__ __align__(16) float g_gates[NB * 4 * DECD];
__device__ __align__(16) float g_hall [NT * NB * DECD];    // h_t, rows m = t*32+b

// ============================================================
// mean over P
// ============================================================
__global__ void mean_kernel(const float* __restrict__ enc, float* __restrict__ mean)
{
    int b = blockIdx.x;
    for (int k = threadIdx.x; k < ENC; k += 256) {
        const float* p0 = enc + (size_t)b * PP * ENC + k;
        float s = 0.f;
        #pragma unroll 4
        for (int p = 0; p < PP; p++) s += p0[(size_t)p * ENC];
        mean[b * ENC + k] = s * (1.0f / PP);
    }
}

// ============================================================
// Big tiled GEMM via TF32 tensor cores:
// C[M,Ntot] = A[M,K] @ W[Ntot,K]^T + bias
// 128x64 block tile, BK=32, mma.m16n8k8 tf32, pipelined global loads.
// 8 warps: wm = warp>>2 (2 x 64 rows), wn = warp&3 (4 x 16 cols).
// remap=0: C[m*ldc+n]. remap=1 (preds): row m=t*32+b -> C[(b*NT+t)*Ntot+n].
// M % 128 == 0, K % 32 == 0. N edge guarded.
// ============================================================
#define AS_LD 132
#define BS_LD 72
__global__ __launch_bounds__(256) void gemm_tc_kernel(
    const float* __restrict__ A, const float* __restrict__ W,
    const float* __restrict__ bias, float* __restrict__ C,
    int K, int Ntot, int ldc, int remap)
{
    __shared__ __align__(16) unsigned As[32 * AS_LD];   // [k][m], tf32 bits
    __shared__ __align__(16) unsigned Bs[32 * BS_LD];   // [k][n], tf32 bits
    const int tid  = threadIdx.x;
    const int m0   = blockIdx.y * 128;
    const int n0   = blockIdx.x * 64;
    const int lane = tid & 31;
    const int warp = tid >> 5;
    const int wm   = warp >> 2;
    const int wn   = warp & 3;
    const int g    = lane >> 2;     // group id 0..7
    const int tig  = lane & 3;      // thread in group 0..3

    float acc[4][2][4];
    #pragma unroll
    for (int i = 0; i < 4; i++)
        #pragma unroll
        for (int j = 0; j < 2; j++)
            #pragma unroll
            for (int q = 0; q < 4; q++) acc[i][j][q] = 0.f;

    float4 av[4], bv[2];
    #pragma unroll
    for (int r = 0; r < 4; r++) {
        int f = tid + r * 256; int m = f >> 3; int c = f & 7;
        av[r] = *(const float4*)(A + (size_t)(m0 + m) * K + c * 4);
    }
    #pragma unroll
    for (int r = 0; r < 2; r++) {
        int f = tid + r * 256; int n = n0 + (f >> 3); int c = f & 7;
        if (n >= Ntot) n = Ntot - 1;
        bv[r] = *(const float4*)(W + (size_t)n * K + c * 4);
    }

    #pragma unroll 1
    for (int k0 = 0; k0 < K; k0 += 32) {
        __syncthreads();
        #pragma unroll
        for (int r = 0; r < 4; r++) {
            int f = tid + r * 256; int m = f >> 3; int c = f & 7;
            As[(c*4+0) * AS_LD + m] = to_tf32(av[r].x);
            As[(c*4+1) * AS_LD + m] = to_tf32(av[r].y);
            As[(c*4+2) * AS_LD + m] = to_tf32(av[r].z);
            As[(c*4+3) * AS_LD + m] = to_tf32(av[r].w);
        }
        #pragma unroll
        for (int r = 0; r < 2; r++) {
            int f = tid + r * 256; int n = f >> 3; int c = f & 7;
            Bs[(c*4+0) * BS_LD + n] = to_tf32(bv[r].x);
            Bs[(c*4+1) * BS_LD + n] = to_tf32(bv[r].y);
            Bs[(c*4+2) * BS_LD + n] = to_tf32(bv[r].z);
            Bs[(c*4+3) * BS_LD + n] = to_tf32(bv[r].w);
        }
        __syncthreads();
        if (k0 + 32 < K) {
            #pragma unroll
            for (int r = 0; r < 4; r++) {
                int f = tid + r * 256; int m = f >> 3; int c = f & 7;
                av[r] = *(const float4*)(A + (size_t)(m0 + m) * K + k0 + 32 + c * 4);
            }
            #pragma unroll
            for (int r = 0; r < 2; r++) {
                int f = tid + r * 256; int n = n0 + (f >> 3); int c = f & 7;
                if (n >= Ntot) n = Ntot - 1;
                bv[r] = *(const float4*)(W + (size_t)n * K + k0 + 32 + c * 4);
            }
        }
        #pragma unroll
        for (int kc = 0; kc < 4; kc++) {
            const int kb = kc * 8;
            unsigned af[4][4], bf2[2][2];
            #pragma unroll
            for (int i = 0; i < 4; i++) {
                int mr = wm * 64 + i * 16 + g;
                af[i][0] = As[(kb + tig)     * AS_LD + mr];
                af[i][1] = As[(kb + tig)     * AS_LD + mr + 8];
                af[i][2] = As[(kb + tig + 4) * AS_LD + mr];
                af[i][3] = As[(kb + tig + 4) * AS_LD + mr + 8];
            }
            #pragma unroll
            for (int j = 0; j < 2; j++) {
                int bn = wn * 16 + j * 8 + g;
                bf2[j][0] = Bs[(kb + tig)     * BS_LD + bn];
                bf2[j][1] = Bs[(kb + tig + 4) * BS_LD + bn];
            }
            #pragma unroll
            for (int i = 0; i < 4; i++)
                #pragma unroll
                for (int j = 0; j < 2; j++) {
                    asm volatile(
                        "mma.sync.aligned.m16n8k8.row.col.f32.tf32.tf32.f32 "
                        "{%0,%1,%2,%3}, {%4,%5,%6,%7}, {%8,%9}, {%0,%1,%2,%3};"
                        : "+f"(acc[i][j][0]), "+f"(acc[i][j][1]),
                          "+f"(acc[i][j][2]), "+f"(acc[i][j][3])
                        : "r"(af[i][0]), "r"(af[i][1]), "r"(af[i][2]), "r"(af[i][3]),
                          "r"(bf2[j][0]), "r"(bf2[j][1]));
                }
        }
    }

    // epilogue
    #pragma unroll
    for (int i = 0; i < 4; i++) {
        int r0 = m0 + wm * 64 + i * 16 + g;
        #pragma unroll
        for (int j = 0; j < 2; j++) {
            int nb = n0 + wn * 16 + j * 8 + tig * 2;
            #pragma unroll
            for (int q = 0; q < 4; q++) {
                int m = r0 + (q >> 1) * 8;
                int n = nb + (q & 1);
                if (n >= Ntot) continue;
                float v = acc[i][j][q] + bias[n];
                if (remap) {
                    int tt = m >> 5, bb = m & 31;
                    C[(size_t)(bb * NT + tt) * Ntot + n] = v;
                } else {
                    C[(size_t)m * ldc + n] = v;
                }
            }
        }
    }
}

// ============================================================
// Skinny GEMM (round-2 proven): out[b][n] = b1[n](+b2[n]) + A1[b]·W1[n] (+A2[b]·W2[n])
// ============================================================
__global__ __launch_bounds__(256) void skinny_gemm_kernel(
    const float* __restrict__ A1, const float* __restrict__ W1, int K1,
    const float* __restrict__ A2, const float* __restrict__ W2, int K2,
    const float* __restrict__ bias1, const float* __restrict__ bias2,
    float* __restrict__ out, int ldc)
{
    __shared__ __align__(16) u64 xs[16][64];
    const int tid  = threadIdx.x;
    const int lane = tid & 31;
    const int w    = tid >> 5;
    const int ng   = w & 3;
    const int bg   = w >> 2;
    const int n0   = blockIdx.x * 16 + ng * 4;
    const int b2s  = tid >> 4;
    const int c4   = tid & 15;

    u64 acc[8][4];
    #pragma unroll
    for (int i = 0; i < 8; i++)
        #pragma unroll
        for (int j = 0; j < 4; j++) acc[i][j] = 0ull;

    #pragma unroll 1
    for (int seg = 0; seg < 2; seg++) {
        const float* A = seg ? A2 : A1;
        const float* W = seg ? W2 : W1;
        const int    K = seg ? K2 : K1;
        if (A == nullptr) continue;
        for (int k0 = 0; k0 < K; k0 += 64) {
            float4 lo4 = *(const float4*)(A + (size_t)(2 * b2s)     * K + k0 + c4 * 4);
            float4 hi4 = *(const float4*)(A + (size_t)(2 * b2s + 1) * K + k0 + c4 * 4);
            __syncthreads();
            xs[b2s][c4*4+0] = pack2(lo4.x, hi4.x);
            xs[b2s][c4*4+1] = pack2(lo4.y, hi4.y);
            xs[b2s][c4*4+2] = pack2(lo4.z, hi4.z);
            xs[b2s][c4*4+3] = pack2(lo4.w, hi4.w);
            __syncthreads();
            const float* wp = W + k0 + lane;
            u64 wd0[4], wd1[4];
            #pragma unroll
            for (int j = 0; j < 4; j++) {
                const float* r = wp + (size_t)(n0 + j) * K;
                float w0 = r[0], w1 = r[32];
                wd0[j] = pack2(w0, w0);
                wd1[j] = pack2(w1, w1);
            }
            #pragma unroll
            for (int i = 0; i < 8; i++) {
                u64 x0 = xs[bg * 8 + i][lane];
                u64 x1 = xs[bg * 8 + i][lane + 32];
                #pragma unroll
                for (int j = 0; j < 4; j++) {
                    acc[i][j] = ffma2(x0, wd0[j], acc[i][j]);
                    acc[i][j] = ffma2(x1, wd1[j], acc[i][j]);
                }
            }
        }
    }
    #pragma unroll
    for (int i = 0; i < 8; i++)
        #pragma unroll
        for (int j = 0; j < 4; j++) {
            u64 v = acc[i][j];
            #pragma unroll
            for (int o = 16; o > 0; o >>= 1)
                v = fadd2(v, __shfl_xor_sync(0xffffffffu, v, o));
            acc[i][j] = v;
        }
    if (lane == 0) {
        #pragma unroll
        for (int i = 0; i < 8; i++) {
            int b = (bg * 8 + i) * 2;
            #pragma unroll
            for (int j = 0; j < 4; j++) {
                int n = n0 + j;
                float bb = bias1[n] + (bias2 ? bias2[n] : 0.0f);
                float lo, hi; unpack2(acc[i][j], lo, hi);
                out[(size_t)b       * ldc + n] = lo + bb;
                out[(size_t)(b + 1) * ldc + n] = hi + bb;
            }
        }
    }
}

// ============================================================
// Fused attention: escore + softmax + alpha writes + embedding gather.
// ============================================================
__global__ void att_fused_kernel(const float* __restrict__ att1,
                                 const float* __restrict__ att2,
                                 const float* __restrict__ Wf,
                                 const float* __restrict__ bf,
                                 float* __restrict__ alpha,
                                 float* __restrict__ out_alpha, int t,
                                 const int* __restrict__ captions,
                                 const float* __restrict__ emb,
                                 float* __restrict__ xbuf)
{
    __shared__ __align__(16) float sA[ATT];
    __shared__ __align__(16) float sW[ATT];
    __shared__ float sE[256];
    __shared__ float red[256];
    __shared__ int s_idx;

    const int b = blockIdx.x, tid = threadIdx.x;

    for (int a = tid; a < ATT; a += 256) {
        sA[a] = att2[(size_t)b * ATT + a];
        sW[a] = Wf[a];
    }
    sE[tid] = -3.4e38f;
    __syncthreads();

    const int w = tid >> 5, lane = tid & 31;
    for (int p = w; p < PP; p += 8) {
        const float4* row = (const float4*)(att1 + ((size_t)b * PP + p) * ATT);
        const float4* a4  = (const float4*)sA;
        const float4* w4  = (const float4*)sW;
        float acc = 0.f;
        #pragma unroll
        for (int c = lane; c < ATT / 4; c += 32) {
            float4 v = row[c], h = a4[c], f = w4[c];
            acc += fmaxf(v.x + h.x, 0.f) * f.x + fmaxf(v.y + h.y, 0.f) * f.y
                 + fmaxf(v.z + h.z, 0.f) * f.z + fmaxf(v.w + h.w, 0.f) * f.w;
        }
        #pragma unroll
        for (int o = 16; o > 0; o >>= 1) acc += __shfl_xor_sync(0xffffffffu, acc, o);
        if (lane == 0) sE[p] = acc + bf[0];
    }
    __syncthreads();

    float v = sE[tid];
    red[tid] = v; __syncthreads();
    #pragma unroll
    for (int s = 128; s > 0; s >>= 1) {
        if (tid < s) red[tid] = fmaxf(red[tid], red[tid + s]);
        __syncthreads();
    }
    float mx = red[0]; __syncthreads();
    float ex = (tid < PP) ? expf(v - mx) : 0.f;
    red[tid] = ex; __syncthreads();
    #pragma unroll
    for (int s = 128; s > 0; s >>= 1) {
        if (tid < s) red[tid] += red[tid + s];
        __syncthreads();
    }
    float inv = 1.0f / red[0];
    if (tid < PP) {
        float a = ex * inv;
        alpha[b * PP + tid] = a;
        out_alpha[(size_t)(b * NT + t) * PP + tid] = a;
    }

    if (tid == 0) {
        // dtype hedge: int64 captions -> every odd 32-bit word is 0
        bool is64 = true;
        #pragma unroll
        for (int i = 0; i < 32; i++)
            if (captions[2 * i + 1] != 0) is64 = false;
        int pos = b * LL + t;
        s_idx = is64 ? captions[2 * pos] : captions[pos];
    }
    __syncthreads();
    xbuf[(size_t)b * XK + tid] = emb[(size_t)s_idx * EMB + tid];  // 256 == EMB
}

// ============================================================
// awe[b][k] = sum_p alpha[b,p] * enc[b,p,k]  -> x buffer at +EMB
// ============================================================
__global__ void awe_kernel(const float* __restrict__ enc,
                           const float* __restrict__ alpha,
                           float* __restrict__ xbuf)
{
    __shared__ float al[PP];
    int b = blockIdx.y;
    int k = blockIdx.x * 256 + threadIdx.x;
    if (threadIdx.x < PP) al[threadIdx.x] = alpha[b * PP + threadIdx.x];
    __syncthreads();
    const float* ep = enc + (size_t)b * PP * ENC + k;
    float acc = 0.f;
    #pragma unroll 4
    for (int p = 0; p < PP; p++) acc += al[p] * ep[(size_t)p * ENC];
    xbuf[(size_t)b * XK + EMB + k] = acc;
}

// ============================================================
// LSTM pointwise (PyTorch gate order i,f,g,o); records h_t into Hall
// ============================================================
__global__ void lstm_kernel(const float* __restrict__ gates,
                            float* __restrict__ h, float* __restrict__ c,
                            float* __restrict__ hall, int t)
{
    int i = blockIdx.x * 256 + threadIdx.x;   // 32*512
    int b = i >> 9, j = i & 511;
    const float* g = gates + (size_t)b * 4 * DECD;
    float ig = g[j], fg = g[DECD + j], gg = g[2 * DECD + j], og = g[3 * DECD + j];
    float si = 1.f / (1.f + expf(-ig));
    float sf = 1.f / (1.f + expf(-fg));
    float so = 1.f / (1.f + expf(-og));
    float cn = sf * c[i] + si * tanhf(gg);
    float hn = so * tanhf(cn);
    c[i] = cn; h[i] = hn;
    hall[(size_t)(t * NB + b) * DECD + j] = hn;
}

// ============================================================
extern "C" void kernel_launch(void* const* d_in, const int* in_sizes, int n_in,
                              void* d_out, int out_size)
{
    const float* enc  = (const float*)d_in[0];
    const int*   caps = (const int*)  d_in[1];
    const float* emb  = (const float*)d_in[3];
    const float* We   = (const float*)d_in[4];
    const float* be   = (const float*)d_in[5];
    const float* Wd   = (const float*)d_in[6];
    const float* bd   = (const float*)d_in[7];
    const float* Wf   = (const float*)d_in[8];
    const float* bf   = (const float*)d_in[9];
    const float* Wih  = (const float*)d_in[10];
    const float* bih  = (const float*)d_in[11];
    const float* Whh  = (const float*)d_in[12];
    const float* bhh  = (const float*)d_in[13];
    const float* Wfc  = (const float*)d_in[14];
    const float* bfc  = (const float*)d_in[15];
    const float* Wh0  = (const float*)d_in[16];
    const float* bh0  = (const float*)d_in[17];
    const float* Wc0  = (const float*)d_in[18];
    const float* bc0  = (const float*)d_in[19];

    float* out       = (float*)d_out;                  // predictions [32,20,30000]
    float* out_alpha = out + (size_t)NB * NT * NV;     // alphas      [32,20,196]

    float *p_att1, *p_mean, *p_h, *p_c, *p_att2, *p_alpha, *p_x, *p_gates, *p_hall;
    cudaGetSymbolAddress((void**)&p_att1,  g_att1);
    cudaGetSymbolAddress((void**)&p_mean,  g_mean);
    cudaGetSymbolAddress((void**)&p_h,     g_h);
    cudaGetSymbolAddress((void**)&p_c,     g_c);
    cudaGetSymbolAddress((void**)&p_att2,  g_att2);
    cudaGetSymbolAddress((void**)&p_alpha, g_alpha);
    cudaGetSymbolAddress((void**)&p_x,     g_x);
    cudaGetSymbolAddress((void**)&p_gates, g_gates);
    cudaGetSymbolAddress((void**)&p_hall,  g_hall);

    // ---- init ----
    mean_kernel<<<NB, 256>>>(enc, p_mean);
    skinny_gemm_kernel<<<DECD / 16, 256>>>(p_mean, Wh0, ENC, nullptr, nullptr, 0,
                                           bh0, nullptr, p_h, DECD);
    skinny_gemm_kernel<<<DECD / 16, 256>>>(p_mean, Wc0, ENC, nullptr, nullptr, 0,
                                           bc0, nullptr, p_c, DECD);
    gemm_tc_kernel<<<dim3(ATT / 64, (NB * PP) / 128), 256>>>(enc, We, be, p_att1,
                                                             ENC, ATT, ATT, 0);

    // ---- decode loop (R4-proven structure) ----
    for (int t = 0; t < NT; t++) {
        skinny_gemm_kernel<<<ATT / 16, 256>>>(p_h, Wd, DECD, nullptr, nullptr, 0,
                                              bd, nullptr, p_att2, ATT);
        att_fused_kernel<<<NB, 256>>>(p_att1, p_att2, Wf, bf, p_alpha,
                                      out_alpha, t, caps, emb, p_x);
        awe_kernel<<<dim3(ENC / 256, NB), 256>>>(enc, p_alpha, p_x);
        skinny_gemm_kernel<<<(4 * DECD) / 16, 256>>>(p_x, Wih, XK, p_h, Whh, DECD,
                                                     bih, bhh, p_gates, 4 * DECD);
        lstm_kernel<<<(NB * DECD) / 256, 256>>>(p_gates, p_h, p_c, p_hall, t);
    }

    // ---- batched predictions: [640,512] @ [512,30000]^T, rows remapped ----
    gemm_tc_kernel<<<dim3((NV + 63) / 64, (NT * NB) / 128), 256>>>(
        p_hall, Wfc, bfc, out, DECD, NV, 0, 1);
}